// round 1
// baseline (speedup 1.0000x reference)
#include <cuda_runtime.h>
#include <math.h>

// Problem dims
#define BB 32
#define TT 256
#define CC 384
#define LL 6
#define NH 6
#define HD 64
#define VV 32000
#define MM (BB*TT)      // 8192
#define FF (4*CC)       // 1536

// Scratch (device globals; no allocations allowed)
__device__ float g_x[MM*CC];
__device__ float g_h[MM*CC];
__device__ float g_q[MM*CC];
__device__ float g_k[MM*CC];
__device__ float g_v[MM*CC];
__device__ float g_att[MM*CC];
__device__ float g_u[MM*FF];

// ---------------------------------------------------------------------------
// Embedding: x[row][c] = tok_emb[idx[row]][c] + pos_emb[row%T][c]
// ---------------------------------------------------------------------------
__global__ void embed_kernel(const int* __restrict__ idx,
                             const float* __restrict__ tok,
                             const float* __restrict__ pos,
                             float* __restrict__ X)
{
    int i = blockIdx.x * blockDim.x + threadIdx.x;   // over MM*96 float4s
    if (i >= MM * (CC/4)) return;
    int row = i / (CC/4);
    int c4  = i % (CC/4);
    int t   = idx[row];
    int p   = row & (TT-1);
    float4 a = *(const float4*)(tok + (size_t)t*CC + c4*4);
    float4 e = *(const float4*)(pos + (size_t)p*CC + c4*4);
    a.x += e.x; a.y += e.y; a.z += e.z; a.w += e.w;
    *(float4*)(X + (size_t)row*CC + c4*4) = a;
}

// ---------------------------------------------------------------------------
// LayerNorm: one warp per row of 384
// ---------------------------------------------------------------------------
__global__ void ln_kernel(const float* __restrict__ X,
                          const float* __restrict__ g,
                          const float* __restrict__ b,
                          float* __restrict__ Y)
{
    int row  = blockIdx.x * 8 + (threadIdx.x >> 5);
    int lane = threadIdx.x & 31;
    if (row >= MM) return;
    const float* x = X + (size_t)row*CC;
    float v[12];
    float s = 0.f, ss = 0.f;
#pragma unroll
    for (int i = 0; i < 12; i++) {
        v[i] = x[lane + i*32];
        s  += v[i];
        ss += v[i]*v[i];
    }
#pragma unroll
    for (int o = 16; o; o >>= 1) {
        s  += __shfl_xor_sync(0xFFFFFFFFu, s,  o);
        ss += __shfl_xor_sync(0xFFFFFFFFu, ss, o);
    }
    float mean = s  * (1.0f/CC);
    float var  = ss * (1.0f/CC) - mean*mean;
    float inv  = rsqrtf(var + 1e-5f);
    float* y = Y + (size_t)row*CC;
#pragma unroll
    for (int i = 0; i < 12; i++) {
        int c = lane + i*32;
        y[c] = (v[i]-mean)*inv*g[c] + b[c];
    }
}

// ---------------------------------------------------------------------------
// SGEMM: C[M,N] = A[M,K] @ B[K,N] (+bias) (+residual) (ReLU)
// 64x64 tile, BK=16, 256 threads, 4x4 microtile.
// All of M%64==0, N%64==0, K%16==0 hold for every call here.
// ---------------------------------------------------------------------------
template<bool RELU, bool RES>
__global__ __launch_bounds__(256)
void sgemm64(const float* __restrict__ A, const float* __restrict__ B,
             const float* __restrict__ bias, const float* __restrict__ res,
             float* __restrict__ C, int M, int N, int K)
{
    __shared__ float As[16][68];
    __shared__ float Bs[16][68];
    const int bm = blockIdx.y * 64;
    const int bn = blockIdx.x * 64;
    const int tid = threadIdx.x;
    const int tx = tid & 15;       // 0..15 -> n
    const int ty = tid >> 4;       // 0..15 -> m
    float acc[4][4] = {};

    for (int k0 = 0; k0 < K; k0 += 16) {
        // A tile: 64 rows x 16 cols -> store transposed
        {
            int r  = tid >> 2;           // 0..63
            int c4 = (tid & 3) * 4;      // 0,4,8,12
            float4 a4 = *(const float4*)(A + (size_t)(bm + r)*K + k0 + c4);
            As[c4+0][r] = a4.x;
            As[c4+1][r] = a4.y;
            As[c4+2][r] = a4.z;
            As[c4+3][r] = a4.w;
        }
        // B tile: 16 rows x 64 cols
        {
            int r  = tid >> 4;           // 0..15
            int c4 = (tid & 15) * 4;
            *(float4*)(&Bs[r][c4]) = *(const float4*)(B + (size_t)(k0 + r)*N + bn + c4);
        }
        __syncthreads();
#pragma unroll
        for (int k = 0; k < 16; k++) {
            float4 a4 = *(const float4*)(&As[k][ty*4]);
            float4 b4 = *(const float4*)(&Bs[k][tx*4]);
            float a[4] = {a4.x, a4.y, a4.z, a4.w};
            float b[4] = {b4.x, b4.y, b4.z, b4.w};
#pragma unroll
            for (int i = 0; i < 4; i++)
#pragma unroll
                for (int j = 0; j < 4; j++)
                    acc[i][j] += a[i]*b[j];
        }
        __syncthreads();
    }

    float bsv[4] = {0.f, 0.f, 0.f, 0.f};
    if (bias) {
#pragma unroll
        for (int j = 0; j < 4; j++) bsv[j] = bias[bn + tx*4 + j];
    }
#pragma unroll
    for (int i = 0; i < 4; i++) {
        int m = bm + ty*4 + i;
        size_t off = (size_t)m*N + bn + tx*4;
        float4 o;
        float rv[4] = {0.f, 0.f, 0.f, 0.f};
        if (RES) {
            float4 r4 = *(const float4*)(res + off);
            rv[0]=r4.x; rv[1]=r4.y; rv[2]=r4.z; rv[3]=r4.w;
        }
        float* po = &o.x;
#pragma unroll
        for (int j = 0; j < 4; j++) {
            float vv = acc[i][j] + bsv[j];
            if (RES)  vv += rv[j];
            if (RELU) vv = fmaxf(vv, 0.f);
            po[j] = vv;
        }
        *(float4*)(C + off) = o;
    }
}

// ---------------------------------------------------------------------------
// Attention: 1 block per (batch, head). K,V tiles in smem (broadcast reads).
// 1 thread per query row, online softmax, causal.
// ---------------------------------------------------------------------------
#define KV_STRIDE 68
#define ATT_SMEM (2 * TT * KV_STRIDE * (int)sizeof(float))

__global__ __launch_bounds__(256, 1)
void attn_kernel(const float* __restrict__ Q, const float* __restrict__ K,
                 const float* __restrict__ V, float* __restrict__ O)
{
    extern __shared__ float sm[];
    float* Ks = sm;
    float* Vs = sm + TT*KV_STRIDE;

    const int bh = blockIdx.x;           // 0..B*NH-1
    const int b  = bh / NH;
    const int h  = bh % NH;
    const float scale = 0.05103103630798288f;  // 1/sqrt(384)

    const float* kbase = K + (size_t)b*TT*CC + h*HD;
    const float* vbase = V + (size_t)b*TT*CC + h*HD;

    // cooperative load of K,V tiles [256 x 64]
    for (int i = threadIdx.x; i < TT*16; i += 256) {
        int t  = i >> 4;
        int d4 = (i & 15) * 4;
        *(float4*)(Ks + t*KV_STRIDE + d4) = *(const float4*)(kbase + (size_t)t*CC + d4);
        *(float4*)(Vs + t*KV_STRIDE + d4) = *(const float4*)(vbase + (size_t)t*CC + d4);
    }
    __syncthreads();

    const int t = threadIdx.x;           // query row
    const float* qrow = Q + (size_t)b*TT*CC + (size_t)t*CC + h*HD;
    float q[HD];
#pragma unroll
    for (int d4 = 0; d4 < 16; d4++) {
        float4 v4 = *(const float4*)(qrow + d4*4);
        q[d4*4+0]=v4.x; q[d4*4+1]=v4.y; q[d4*4+2]=v4.z; q[d4*4+3]=v4.w;
    }

    float m = -1e30f, l = 0.f;
    float acc[HD];
#pragma unroll
    for (int d = 0; d < HD; d++) acc[d] = 0.f;

    for (int s = 0; s <= t; s++) {
        const float* kr = Ks + s*KV_STRIDE;
        float dot = 0.f;
#pragma unroll
        for (int d4 = 0; d4 < 16; d4++) {
            float4 kv = *(const float4*)(kr + d4*4);
            dot += q[d4*4+0]*kv.x + q[d4*4+1]*kv.y + q[d4*4+2]*kv.z + q[d4*4+3]*kv.w;
        }
        dot *= scale;
        float mn   = fmaxf(m, dot);
        float corr = __expf(m - mn);
        float p    = __expf(dot - mn);
        l = l*corr + p;
        const float* vr = Vs + s*KV_STRIDE;
#pragma unroll
        for (int d4 = 0; d4 < 16; d4++) {
            float4 vv = *(const float4*)(vr + d4*4);
            acc[d4*4+0] = acc[d4*4+0]*corr + p*vv.x;
            acc[d4*4+1] = acc[d4*4+1]*corr + p*vv.y;
            acc[d4*4+2] = acc[d4*4+2]*corr + p*vv.z;
            acc[d4*4+3] = acc[d4*4+3]*corr + p*vv.w;
        }
        m = mn;
    }

    float inv = 1.f / l;
    float* orow = O + (size_t)b*TT*CC + (size_t)t*CC + h*HD;
#pragma unroll
    for (int d4 = 0; d4 < 16; d4++) {
        float4 o;
        o.x = acc[d4*4+0]*inv; o.y = acc[d4*4+1]*inv;
        o.z = acc[d4*4+2]*inv; o.w = acc[d4*4+3]*inv;
        *(float4*)(orow + d4*4) = o;
    }
}

// ---------------------------------------------------------------------------
// Host
// ---------------------------------------------------------------------------
static void gemm(const float* A, const float* B, const float* bias, const float* res,
                 float* C, int M, int N, int K, bool relu, bool hasRes)
{
    dim3 grid(N/64, M/64);
    if (relu)        sgemm64<true,  false><<<grid, 256>>>(A, B, bias, res, C, M, N, K);
    else if (hasRes) sgemm64<false, true ><<<grid, 256>>>(A, B, bias, res, C, M, N, K);
    else             sgemm64<false, false><<<grid, 256>>>(A, B, bias, res, C, M, N, K);
}

extern "C" void kernel_launch(void* const* d_in, const int* in_sizes, int n_in,
                              void* d_out, int out_size)
{
    (void)in_sizes; (void)n_in; (void)out_size;

    const int*   idx     = (const int*)  d_in[0];
    const float* tok_emb = (const float*)d_in[1];
    const float* pos_emb = (const float*)d_in[2];
    const float* ln1_g   = (const float*)d_in[3];
    const float* ln1_b   = (const float*)d_in[4];
    const float* wq      = (const float*)d_in[5];
    const float* wk      = (const float*)d_in[6];
    const float* wv      = (const float*)d_in[7];
    const float* wo      = (const float*)d_in[8];
    const float* wo_b    = (const float*)d_in[9];
    const float* ln2_g   = (const float*)d_in[10];
    const float* ln2_b   = (const float*)d_in[11];
    const float* w1      = (const float*)d_in[12];
    const float* b1      = (const float*)d_in[13];
    const float* w2      = (const float*)d_in[14];
    const float* b2      = (const float*)d_in[15];
    const float* lnf_g   = (const float*)d_in[16];
    const float* lnf_b   = (const float*)d_in[17];
    const float* lm_w    = (const float*)d_in[18];
    const float* lm_b    = (const float*)d_in[19];
    float* out = (float*)d_out;

    float *x, *h, *q, *k, *v, *att, *u;
    cudaGetSymbolAddress((void**)&x,   g_x);
    cudaGetSymbolAddress((void**)&h,   g_h);
    cudaGetSymbolAddress((void**)&q,   g_q);
    cudaGetSymbolAddress((void**)&k,   g_k);
    cudaGetSymbolAddress((void**)&v,   g_v);
    cudaGetSymbolAddress((void**)&att, g_att);
    cudaGetSymbolAddress((void**)&u,   g_u);

    cudaFuncSetAttribute(attn_kernel, cudaFuncAttributeMaxDynamicSharedMemorySize, ATT_SMEM);

    // embedding
    {
        int total = MM * (CC/4);
        embed_kernel<<<(total + 255)/256, 256>>>(idx, tok_emb, pos_emb, x);
    }

    for (int L = 0; L < LL; L++) {
        const float* g1  = ln1_g + (size_t)L*CC;
        const float* bg1 = ln1_b + (size_t)L*CC;
        const float* Wq  = wq   + (size_t)L*CC*CC;
        const float* Wk  = wk   + (size_t)L*CC*CC;
        const float* Wv  = wv   + (size_t)L*CC*CC;
        const float* Wo  = wo   + (size_t)L*CC*CC;
        const float* Wob = wo_b + (size_t)L*CC;
        const float* g2  = ln2_g + (size_t)L*CC;
        const float* bg2 = ln2_b + (size_t)L*CC;
        const float* W1  = w1 + (size_t)L*CC*FF;
        const float* B1  = b1 + (size_t)L*FF;
        const float* W2  = w2 + (size_t)L*FF*CC;
        const float* B2  = b2 + (size_t)L*CC;

        ln_kernel<<<MM/8, 256>>>(x, g1, bg1, h);
        gemm(h, Wq, nullptr, nullptr, q, MM, CC, CC, false, false);
        gemm(h, Wk, nullptr, nullptr, k, MM, CC, CC, false, false);
        gemm(h, Wv, nullptr, nullptr, v, MM, CC, CC, false, false);
        attn_kernel<<<BB*NH, 256, ATT_SMEM>>>(q, k, v, att);
        gemm(att, Wo, Wob, x, x, MM, CC, CC, false, true);      // x += att@Wo + b
        ln_kernel<<<MM/8, 256>>>(x, g2, bg2, h);
        gemm(h, W1, B1, nullptr, u, MM, FF, CC, true, false);   // u = relu(h@W1+b1)
        gemm(u, W2, B2, x, x, MM, CC, FF, false, true);         // x += u@W2 + b2
    }

    ln_kernel<<<MM/8, 256>>>(x, lnf_g, lnf_b, h);
    gemm(h, lm_w, lm_b, nullptr, out, MM, VV, CC, false, false);
}

// round 2
// speedup vs baseline: 2.6622x; 2.6622x over previous
#include <cuda_runtime.h>
#include <math.h>
#include <stdint.h>

// Problem dims
#define BB 32
#define TT 256
#define CC 384
#define LL 6
#define NH 6
#define HD 64
#define VV 32000
#define MM (BB*TT)      // 8192
#define FF (4*CC)       // 1536

// Scratch (device globals; no allocations allowed)
__device__ float g_x[MM*CC];
__device__ float g_h[MM*CC];
__device__ float g_q[MM*CC];
__device__ float g_k[MM*CC];
__device__ float g_v[MM*CC];
__device__ float g_att[MM*CC];
__device__ float g_u[MM*FF];

// ---------------------------------------------------------------------------
// Helpers
// ---------------------------------------------------------------------------
__device__ __forceinline__ uint32_t f2tf(float f) {
    uint32_t u;
    asm("cvt.rna.tf32.f32 %0, %1;" : "=r"(u) : "f"(f));
    return u;
}

__device__ __forceinline__ void mma_tf32(float* c, const uint32_t* a, const uint32_t* b) {
    asm volatile(
        "mma.sync.aligned.m16n8k8.row.col.f32.tf32.tf32.f32 "
        "{%0,%1,%2,%3}, {%4,%5,%6,%7}, {%8,%9}, {%0,%1,%2,%3};"
        : "+f"(c[0]), "+f"(c[1]), "+f"(c[2]), "+f"(c[3])
        : "r"(a[0]), "r"(a[1]), "r"(a[2]), "r"(a[3]),
          "r"(b[0]), "r"(b[1]));
}

// ---------------------------------------------------------------------------
// Embedding: x[row][c] = tok_emb[idx[row]][c] + pos_emb[row%T][c]
// ---------------------------------------------------------------------------
__global__ void embed_kernel(const int* __restrict__ idx,
                             const float* __restrict__ tok,
                             const float* __restrict__ pos,
                             float* __restrict__ X)
{
    int i = blockIdx.x * blockDim.x + threadIdx.x;
    if (i >= MM * (CC/4)) return;
    int row = i / (CC/4);
    int c4  = i % (CC/4);
    int t   = idx[row];
    int p   = row & (TT-1);
    float4 a = *(const float4*)(tok + (size_t)t*CC + c4*4);
    float4 e = *(const float4*)(pos + (size_t)p*CC + c4*4);
    a.x += e.x; a.y += e.y; a.z += e.z; a.w += e.w;
    *(float4*)(X + (size_t)row*CC + c4*4) = a;
}

// ---------------------------------------------------------------------------
// LayerNorm: one warp per row of 384
// ---------------------------------------------------------------------------
__global__ void ln_kernel(const float* __restrict__ X,
                          const float* __restrict__ g,
                          const float* __restrict__ b,
                          float* __restrict__ Y)
{
    int row  = blockIdx.x * 8 + (threadIdx.x >> 5);
    int lane = threadIdx.x & 31;
    if (row >= MM) return;
    const float* x = X + (size_t)row*CC;
    float v[12];
    float s = 0.f, ss = 0.f;
#pragma unroll
    for (int i = 0; i < 12; i++) {
        v[i] = x[lane + i*32];
        s  += v[i];
        ss += v[i]*v[i];
    }
#pragma unroll
    for (int o = 16; o; o >>= 1) {
        s  += __shfl_xor_sync(0xFFFFFFFFu, s,  o);
        ss += __shfl_xor_sync(0xFFFFFFFFu, ss, o);
    }
    float mean = s  * (1.0f/CC);
    float var  = ss * (1.0f/CC) - mean*mean;
    float inv  = rsqrtf(var + 1e-5f);
    float* y = Y + (size_t)row*CC;
#pragma unroll
    for (int i = 0; i < 12; i++) {
        int c = lane + i*32;
        y[c] = (v[i]-mean)*inv*g[c] + b[c];
    }
}

// ---------------------------------------------------------------------------
// TF32 tensor-core GEMM: C[M,N] = A[M,K] @ B[K,N] (+bias)(+residual)(ReLU)
// Block tile 128x128, BK=32, 256 threads (8 warps), each warp 64x32.
// mma.sync m16n8k8 tf32. Requires M%128==0, N%128==0, K%32==0 (all hold).
// Smem strides: As 36 (bank-conflict-free A frags), Bs 136 (conflict-free B).
// ---------------------------------------------------------------------------
template<bool RELU, bool RES>
__global__ __launch_bounds__(256)
void tgemm(const float* __restrict__ A, const float* __restrict__ B,
           const float* __restrict__ bias, const float* __restrict__ res,
           float* __restrict__ C, int M, int N, int K)
{
    __shared__ uint32_t As[128][36];
    __shared__ uint32_t Bs[32][136];

    const int bm = blockIdx.y * 128;
    const int bn = blockIdx.x * 128;
    const int tid  = threadIdx.x;
    const int lane = tid & 31;
    const int wid  = tid >> 5;
    const int wm = (wid & 1) * 64;     // warp row offset within block
    const int wn = (wid >> 1) * 32;    // warp col offset within block
    const int grp = lane >> 2;         // 0..7
    const int tg  = lane & 3;          // 0..3

    float acc[4][4][4];
#pragma unroll
    for (int mt = 0; mt < 4; mt++)
#pragma unroll
        for (int nt = 0; nt < 4; nt++)
#pragma unroll
            for (int e = 0; e < 4; e++) acc[mt][nt][e] = 0.f;

    for (int k0 = 0; k0 < K; k0 += 32) {
        // A tile: 128 x 32 floats = 1024 float4, 4 per thread
#pragma unroll
        for (int p = 0; p < 4; p++) {
            int i  = tid + p*256;
            int r  = i >> 3;
            int c4 = (i & 7) * 4;
            float4 v = *(const float4*)(A + (size_t)(bm + r)*K + k0 + c4);
            uint4 u;
            u.x = f2tf(v.x); u.y = f2tf(v.y); u.z = f2tf(v.z); u.w = f2tf(v.w);
            *(uint4*)&As[r][c4] = u;
        }
        // B tile: 32 x 128 floats = 1024 float4, 4 per thread
#pragma unroll
        for (int p = 0; p < 4; p++) {
            int i  = tid + p*256;
            int r  = i >> 5;
            int c4 = (i & 31) * 4;
            float4 v = *(const float4*)(B + (size_t)(k0 + r)*N + bn + c4);
            uint4 u;
            u.x = f2tf(v.x); u.y = f2tf(v.y); u.z = f2tf(v.z); u.w = f2tf(v.w);
            *(uint4*)&Bs[r][c4] = u;
        }
        __syncthreads();

#pragma unroll
        for (int kk = 0; kk < 32; kk += 8) {
            uint32_t af[4][4], bf[4][2];
#pragma unroll
            for (int mt = 0; mt < 4; mt++) {
                int r = wm + mt*16 + grp;
                af[mt][0] = As[r    ][kk + tg    ];
                af[mt][1] = As[r + 8][kk + tg    ];
                af[mt][2] = As[r    ][kk + tg + 4];
                af[mt][3] = As[r + 8][kk + tg + 4];
            }
#pragma unroll
            for (int nt = 0; nt < 4; nt++) {
                int c = wn + nt*8 + grp;
                bf[nt][0] = Bs[kk + tg    ][c];
                bf[nt][1] = Bs[kk + tg + 4][c];
            }
#pragma unroll
            for (int mt = 0; mt < 4; mt++)
#pragma unroll
                for (int nt = 0; nt < 4; nt++)
                    mma_tf32(acc[mt][nt], af[mt], bf[nt]);
        }
        __syncthreads();
    }

    // Epilogue
#pragma unroll
    for (int mt = 0; mt < 4; mt++) {
        int r0 = bm + wm + mt*16 + grp;
        int r1 = r0 + 8;
#pragma unroll
        for (int nt = 0; nt < 4; nt++) {
            int c = bn + wn + nt*8 + tg*2;
            float o0x = acc[mt][nt][0], o0y = acc[mt][nt][1];
            float o1x = acc[mt][nt][2], o1y = acc[mt][nt][3];
            if (bias) {
                float bv0 = bias[c], bv1 = bias[c+1];
                o0x += bv0; o0y += bv1; o1x += bv0; o1y += bv1;
            }
            if (RES) {
                float2 ra = *(const float2*)(res + (size_t)r0*N + c);
                float2 rb = *(const float2*)(res + (size_t)r1*N + c);
                o0x += ra.x; o0y += ra.y; o1x += rb.x; o1y += rb.y;
            }
            if (RELU) {
                o0x = fmaxf(o0x, 0.f); o0y = fmaxf(o0y, 0.f);
                o1x = fmaxf(o1x, 0.f); o1y = fmaxf(o1y, 0.f);
            }
            float2 w0 = {o0x, o0y};
            float2 w1 = {o1x, o1y};
            *(float2*)(C + (size_t)r0*N + c) = w0;
            *(float2*)(C + (size_t)r1*N + c) = w1;
        }
    }
}

// ---------------------------------------------------------------------------
// Attention: 1 block per (batch, head). K,V tiles in smem (broadcast reads).
// 1 thread per query row, online softmax, causal.
// ---------------------------------------------------------------------------
#define KV_STRIDE 68
#define ATT_SMEM (2 * TT * KV_STRIDE * (int)sizeof(float))

__global__ __launch_bounds__(256, 1)
void attn_kernel(const float* __restrict__ Q, const float* __restrict__ K,
                 const float* __restrict__ V, float* __restrict__ O)
{
    extern __shared__ float sm[];
    float* Ks = sm;
    float* Vs = sm + TT*KV_STRIDE;

    const int bh = blockIdx.x;
    const int b  = bh / NH;
    const int h  = bh % NH;
    const float scale = 0.05103103630798288f;  // 1/sqrt(384)

    const float* kbase = K + (size_t)b*TT*CC + h*HD;
    const float* vbase = V + (size_t)b*TT*CC + h*HD;

    for (int i = threadIdx.x; i < TT*16; i += 256) {
        int t  = i >> 4;
        int d4 = (i & 15) * 4;
        *(float4*)(Ks + t*KV_STRIDE + d4) = *(const float4*)(kbase + (size_t)t*CC + d4);
        *(float4*)(Vs + t*KV_STRIDE + d4) = *(const float4*)(vbase + (size_t)t*CC + d4);
    }
    __syncthreads();

    const int t = threadIdx.x;
    const float* qrow = Q + (size_t)b*TT*CC + (size_t)t*CC + h*HD;
    float q[HD];
#pragma unroll
    for (int d4 = 0; d4 < 16; d4++) {
        float4 v4 = *(const float4*)(qrow + d4*4);
        q[d4*4+0]=v4.x; q[d4*4+1]=v4.y; q[d4*4+2]=v4.z; q[d4*4+3]=v4.w;
    }

    float m = -1e30f, l = 0.f;
    float acc[HD];
#pragma unroll
    for (int d = 0; d < HD; d++) acc[d] = 0.f;

    for (int s = 0; s <= t; s++) {
        const float* kr = Ks + s*KV_STRIDE;
        float dot = 0.f;
#pragma unroll
        for (int d4 = 0; d4 < 16; d4++) {
            float4 kv = *(const float4*)(kr + d4*4);
            dot += q[d4*4+0]*kv.x + q[d4*4+1]*kv.y + q[d4*4+2]*kv.z + q[d4*4+3]*kv.w;
        }
        dot *= scale;
        float mn   = fmaxf(m, dot);
        float corr = __expf(m - mn);
        float p    = __expf(dot - mn);
        l = l*corr + p;
        const float* vr = Vs + s*KV_STRIDE;
#pragma unroll
        for (int d4 = 0; d4 < 16; d4++) {
            float4 vv = *(const float4*)(vr + d4*4);
            acc[d4*4+0] = acc[d4*4+0]*corr + p*vv.x;
            acc[d4*4+1] = acc[d4*4+1]*corr + p*vv.y;
            acc[d4*4+2] = acc[d4*4+2]*corr + p*vv.z;
            acc[d4*4+3] = acc[d4*4+3]*corr + p*vv.w;
        }
        m = mn;
    }

    float inv = 1.f / l;
    float* orow = O + (size_t)b*TT*CC + (size_t)t*CC + h*HD;
#pragma unroll
    for (int d4 = 0; d4 < 16; d4++) {
        float4 o;
        o.x = acc[d4*4+0]*inv; o.y = acc[d4*4+1]*inv;
        o.z = acc[d4*4+2]*inv; o.w = acc[d4*4+3]*inv;
        *(float4*)(orow + d4*4) = o;
    }
}

// ---------------------------------------------------------------------------
// Host
// ---------------------------------------------------------------------------
static void gemm(const float* A, const float* B, const float* bias, const float* res,
                 float* C, int M, int N, int K, bool relu, bool hasRes)
{
    dim3 grid(N/128, M/128);
    if (relu)        tgemm<true,  false><<<grid, 256>>>(A, B, bias, res, C, M, N, K);
    else if (hasRes) tgemm<false, true ><<<grid, 256>>>(A, B, bias, res, C, M, N, K);
    else             tgemm<false, false><<<grid, 256>>>(A, B, bias, res, C, M, N, K);
}

extern "C" void kernel_launch(void* const* d_in, const int* in_sizes, int n_in,
                              void* d_out, int out_size)
{
    (void)in_sizes; (void)n_in; (void)out_size;

    const int*   idx     = (const int*)  d_in[0];
    const float* tok_emb = (const float*)d_in[1];
    const float* pos_emb = (const float*)d_in[2];
    const float* ln1_g   = (const float*)d_in[3];
    const float* ln1_b   = (const float*)d_in[4];
    const float* wq      = (const float*)d_in[5];
    const float* wk      = (const float*)d_in[6];
    const float* wv      = (const float*)d_in[7];
    const float* wo      = (const float*)d_in[8];
    const float* wo_b    = (const float*)d_in[9];
    const float* ln2_g   = (const float*)d_in[10];
    const float* ln2_b   = (const float*)d_in[11];
    const float* w1      = (const float*)d_in[12];
    const float* b1      = (const float*)d_in[13];
    const float* w2      = (const float*)d_in[14];
    const float* b2      = (const float*)d_in[15];
    const float* lnf_g   = (const float*)d_in[16];
    const float* lnf_b   = (const float*)d_in[17];
    const float* lm_w    = (const float*)d_in[18];
    const float* lm_b    = (const float*)d_in[19];
    float* out = (float*)d_out;

    float *x, *h, *q, *k, *v, *att, *u;
    cudaGetSymbolAddress((void**)&x,   g_x);
    cudaGetSymbolAddress((void**)&h,   g_h);
    cudaGetSymbolAddress((void**)&q,   g_q);
    cudaGetSymbolAddress((void**)&k,   g_k);
    cudaGetSymbolAddress((void**)&v,   g_v);
    cudaGetSymbolAddress((void**)&att, g_att);
    cudaGetSymbolAddress((void**)&u,   g_u);

    cudaFuncSetAttribute(attn_kernel, cudaFuncAttributeMaxDynamicSharedMemorySize, ATT_SMEM);

    {
        int total = MM * (CC/4);
        embed_kernel<<<(total + 255)/256, 256>>>(idx, tok_emb, pos_emb, x);
    }

    for (int L = 0; L < LL; L++) {
        const float* g1  = ln1_g + (size_t)L*CC;
        const float* bg1 = ln1_b + (size_t)L*CC;
        const float* Wq  = wq   + (size_t)L*CC*CC;
        const float* Wk  = wk   + (size_t)L*CC*CC;
        const float* Wv  = wv   + (size_t)L*CC*CC;
        const float* Wo  = wo   + (size_t)L*CC*CC;
        const float* Wob = wo_b + (size_t)L*CC;
        const float* g2  = ln2_g + (size_t)L*CC;
        const float* bg2 = ln2_b + (size_t)L*CC;
        const float* W1  = w1 + (size_t)L*CC*FF;
        const float* B1  = b1 + (size_t)L*FF;
        const float* W2  = w2 + (size_t)L*FF*CC;
        const float* B2  = b2 + (size_t)L*CC;

        ln_kernel<<<MM/8, 256>>>(x, g1, bg1, h);
        gemm(h, Wq, nullptr, nullptr, q, MM, CC, CC, false, false);
        gemm(h, Wk, nullptr, nullptr, k, MM, CC, CC, false, false);
        gemm(h, Wv, nullptr, nullptr, v, MM, CC, CC, false, false);
        attn_kernel<<<BB*NH, 256, ATT_SMEM>>>(q, k, v, att);
        gemm(att, Wo, Wob, x, x, MM, CC, CC, false, true);
        ln_kernel<<<MM/8, 256>>>(x, g2, bg2, h);
        gemm(h, W1, B1, nullptr, u, MM, FF, CC, true, false);
        gemm(u, W2, B2, x, x, MM, CC, FF, false, true);
    }

    ln_kernel<<<MM/8, 256>>>(x, lnf_g, lnf_b, h);
    gemm(h, lm_w, lm_b, nullptr, out, MM, VV, CC, false, false);
}